// round 13
// baseline (speedup 1.0000x reference)
#include <cuda_runtime.h>
#include <math.h>
#include <stdint.h>

#define NN    20000
#define KK    32
#define DD    128
#define VOCAB 100000

// ---------------- scratch (static device globals: allocation-free) ----------------
__device__ float g_T[(size_t)VOCAB * DD];   // T[v][d] = sum_i u2e[v][i] * W1[d, i]
__device__ float g_C[(size_t)NN * DD];      // C[n][d] = b1[d] + sum_i self[i] * W1[d, 128+i]
__device__ float g_W1aT[DD * DD];           // [i][d] = W1[d*256 + i]
__device__ float g_W1bT[DD * DD];           // [i][d] = W1[d*256 + 128 + i]
__device__ float g_W2T[DD * DD];            // [k][e] = W2[e*128 + k]  (reduction-major)

#define ASTRIDE 132         // A-fragment LDS conflict-free
#define BSTRIDE 136         // B-fragment LDS conflict-free

// ---------------- smem layouts ----------------
struct SM3 {                // merged T/C precompute: 2 groups x 64 rows, both weight mats
    uint32_t b[2][DD * BSTRIDE];    // tf32 W1aT / W1bT
    uint32_t a[2][64 * ASTRIDE];    // per-group gathered rows
};
struct SK4 {                // main kernel: 4 groups x (2 nodes = 64 edge rows)
    uint32_t b[DD * BSTRIDE];       // tf32 W2T (shared by all groups)   69632 B
    uint32_t a[4][64 * ASTRIDE];    // per-group tf32 h1                135168 B
    float b2s[DD];
    float w3s[DD];
    float logit[4][64];
    float att[4][64];
    int   idx[4][64];
};

__device__ __forceinline__ void gsync2(int g) {     // 8-warp group barrier (mlp kernel)
    asm volatile("bar.sync %0, 256;" :: "r"(g + 1) : "memory");
}
__device__ __forceinline__ void gsync4(int g) {     // 4-warp group barrier (graphrec)
    asm volatile("bar.sync %0, 128;" :: "r"(g + 1) : "memory");
}
__device__ __forceinline__ float wmaxf(float v) {
    #pragma unroll
    for (int o = 16; o; o >>= 1) v = fmaxf(v, __shfl_xor_sync(0xffffffffu, v, o));
    return v;
}
__device__ __forceinline__ float wsumf(float v) {
    #pragma unroll
    for (int o = 16; o; o >>= 1) v += __shfl_xor_sync(0xffffffffu, v, o);
    return v;
}
__device__ __forceinline__ uint32_t f2tf32(float f) {
    uint32_t r;
    asm("cvt.rna.tf32.f32 %0, %1;" : "=r"(r) : "f"(f));
    return r;
}
__device__ __forceinline__ void mma_tf32(float c[4],
                                         uint32_t a0, uint32_t a1, uint32_t a2, uint32_t a3,
                                         uint32_t b0, uint32_t b1) {
    asm volatile(
        "mma.sync.aligned.m16n8k8.row.col.f32.tf32.tf32.f32 "
        "{%0,%1,%2,%3}, {%4,%5,%6,%7}, {%8,%9}, {%0,%1,%2,%3};"
        : "+f"(c[0]), "+f"(c[1]), "+f"(c[2]), "+f"(c[3])
        : "r"(a0), "r"(a1), "r"(a2), "r"(a3), "r"(b0), "r"(b1));
}

// ---------------- K0: transpose weights into reduction-major global copies ----------------
__global__ void prep_kernel(const float* __restrict__ W1, const float* __restrict__ W2) {
    int t = blockIdx.x * blockDim.x + threadIdx.x;
    if (t < DD * DD) {
        int e = t & 127;     // output column
        int i = t >> 7;      // reduction index
        g_W1aT[t] = W1[e * 256 + i];
        g_W1bT[t] = W1[e * 256 + 128 + i];
        g_W2T[t]  = W2[e * 128 + i];
    }
}

// ---------------- K1: merged tf32 precompute of T and C, 2 warp-groups per block ----------------
__global__ __launch_bounds__(512, 1)
void mlp_tc2_kernel(const float* __restrict__ u2e, const int* __restrict__ nodes,
                    const float* __restrict__ b1, int tasksT, int tasksAll) {
    extern __shared__ unsigned char smem_raw[];
    SM3* s = reinterpret_cast<SM3*>(smem_raw);
    int t = threadIdx.x;
    int w = t >> 5, lane = t & 31;
    int grp = lane >> 2, tig = lane & 3;
    int g = w >> 3, wg = w & 7, tg = t & 255;
    int rw = (wg & 3) * 16;        // warp row block within 64
    int cw = (wg >> 2) * 64;       // warp col block within 128

    for (int q = t; q < DD * DD; q += 512) {
        int k = q >> 7, n = q & 127;
        s->b[0][k * BSTRIDE + n] = f2tf32(g_W1aT[q]);
        s->b[1][k * BSTRIDE + n] = f2tf32(g_W1bT[q]);
    }
    __syncthreads();

    for (int task = blockIdx.x * 2 + g; task < tasksAll; task += gridDim.x * 2) {
        gsync2(g);   // previous MMA reads of s->a[g] done before refill

        int isC   = task >= tasksT;
        int taskL = isC ? task - tasksT : task;
        int nrows = isC ? NN : VOCAB;

        // fill a[g]: 4 threads per row, each 32 contiguous floats
        {
            int r = tg >> 2, q = tg & 3;
            int row = taskL * 64 + r;
            bool ok = row < nrows;
            int rowid = ok ? (isC ? nodes[row] : row) : 0;
            const float4* frow = reinterpret_cast<const float4*>(u2e + (size_t)rowid * DD) + q * 8;
            uint4* dst = reinterpret_cast<uint4*>(s->a[g] + r * ASTRIDE + q * 32);
            #pragma unroll
            for (int j = 0; j < 8; j++) {
                float4 v = ok ? frow[j] : make_float4(0.f, 0.f, 0.f, 0.f);
                uint4 o;
                o.x = f2tf32(v.x); o.y = f2tf32(v.y);
                o.z = f2tf32(v.z); o.w = f2tf32(v.w);
                dst[j] = o;
            }
        }
        gsync2(g);

        const uint32_t* __restrict__ B = s->b[isC];
        float acc[8][4];
        #pragma unroll
        for (int nt = 0; nt < 8; nt++)
            #pragma unroll
            for (int c = 0; c < 4; c++) acc[nt][c] = 0.f;

        #pragma unroll
        for (int k0 = 0; k0 < DD; k0 += 8) {
            const uint32_t* ar0 = s->a[g] + (rw + grp) * ASTRIDE + k0 + tig;
            const uint32_t* ar1 = ar0 + 8 * ASTRIDE;
            uint32_t a0 = ar0[0];
            uint32_t a2 = ar0[4];
            uint32_t a1 = ar1[0];
            uint32_t a3 = ar1[4];
            const uint32_t* br0 = B + (k0 + tig) * BSTRIDE + cw + grp;
            const uint32_t* br1 = br0 + 4 * BSTRIDE;
            #pragma unroll
            for (int nt = 0; nt < 8; nt++) {
                mma_tf32(acc[nt], a0, a1, a2, a3, br0[nt * 8], br1[nt * 8]);
            }
        }

        float* __restrict__ out = isC ? g_C : g_T;
        int row0 = taskL * 64 + rw + grp;
        int row1 = row0 + 8;
        #pragma unroll
        for (int nt = 0; nt < 8; nt++) {
            int c0 = cw + nt * 8 + tig * 2;
            float ba = isC ? b1[c0] : 0.f;
            float bb = isC ? b1[c0 + 1] : 0.f;
            if (row0 < nrows)
                *reinterpret_cast<float2*>(out + (size_t)row0 * DD + c0) =
                    make_float2(acc[nt][0] + ba, acc[nt][1] + bb);
            if (row1 < nrows)
                *reinterpret_cast<float2*>(out + (size_t)row1 * DD + c0) =
                    make_float2(acc[nt][2] + ba, acc[nt][3] + bb);
        }
    }
}

// ---------------- K3: 4 warp-groups per block, 2 nodes (64 rows) per task,
//                     warp tile M32xN64 (halves B-fragment smem traffic per node) ----------------
__global__ __launch_bounds__(512, 1)
void graphrec_kernel(const float* __restrict__ u2e, const int* __restrict__ nodes,
                     const int* __restrict__ nidx, const int* __restrict__ nlen,
                     const float* __restrict__ b2, const float* __restrict__ W3,
                     const float* __restrict__ b3, float* __restrict__ out,
                     int ntasks) {
    extern __shared__ unsigned char smem_raw[];
    SK4* s = reinterpret_cast<SK4*>(smem_raw);
    int t = threadIdx.x;
    int w = t >> 5, lane = t & 31;
    int grp = lane >> 2, tig = lane & 3;
    int g = w >> 2, wg = w & 3, tg = t & 127;
    int mw = (wg & 1) * 32;        // warp row block (32 rows) within 64
    int cw = (wg >> 1) * 64;       // warp col block (64 cols) within 128

    // ---- one-time per block: stage W2T (tf32), b2, W3 ----
    for (int q = t; q < DD * DD; q += 512) {
        int k = q >> 7, n = q & 127;
        s->b[k * BSTRIDE + n] = f2tf32(g_W2T[q]);
    }
    if (t < DD) { s->b2s[t] = b2[t]; s->w3s[t] = W3[t]; }
    float b3v = b3[0];
    __syncthreads();

    for (int task = blockIdx.x * 4 + g; task < ntasks; task += gridDim.x * 4) {
        gsync4(g);   // prev iteration's reads of this group's smem complete

        // ---- fill h1 (tf32): 2 threads per row, 64 contiguous floats each.
        //      idx staged + logit zeroed in the same phase.
        {
            int r = tg >> 1, q = tg & 1;
            int vrow = nidx[task * 64 + r];
            if (tg < 64) { s->idx[g][tg] = nidx[task * 64 + tg]; s->logit[g][tg] = 0.f; }
            int n = task * 2 + (r >> 5);
            const float4* trow = reinterpret_cast<const float4*>(g_T + (size_t)vrow * DD) + q * 16;
            const float4* crow = reinterpret_cast<const float4*>(g_C + (size_t)n * DD) + q * 16;
            uint4* dst = reinterpret_cast<uint4*>(s->a[g] + r * ASTRIDE + q * 64);
            #pragma unroll
            for (int j = 0; j < 16; j++) {
                float4 tv = trow[j];
                float4 cv = crow[j];
                uint4 o;
                o.x = f2tf32(fmaxf(tv.x + cv.x, 0.f));
                o.y = f2tf32(fmaxf(tv.y + cv.y, 0.f));
                o.z = f2tf32(fmaxf(tv.z + cv.z, 0.f));
                o.w = f2tf32(fmaxf(tv.w + cv.w, 0.f));
                dst[j] = o;
            }
        }
        gsync4(g);

        // ---- tensor-core mainloop: 16 k-steps x (2 m-tiles x 8 n-tiles) ----
        float acc[2][8][4];
        #pragma unroll
        for (int mt = 0; mt < 2; mt++)
            #pragma unroll
            for (int nt = 0; nt < 8; nt++)
                #pragma unroll
                for (int c = 0; c < 4; c++) acc[mt][nt][c] = 0.f;

        #pragma unroll
        for (int k0 = 0; k0 < DD; k0 += 8) {
            uint32_t a0[2], a1[2], a2[2], a3[2];
            #pragma unroll
            for (int mt = 0; mt < 2; mt++) {
                const uint32_t* ar0 = s->a[g] + (mw + mt * 16 + grp) * ASTRIDE + k0 + tig;
                const uint32_t* ar1 = ar0 + 8 * ASTRIDE;
                a0[mt] = ar0[0];
                a2[mt] = ar0[4];
                a1[mt] = ar1[0];
                a3[mt] = ar1[4];
            }
            const uint32_t* br0 = s->b + (k0 + tig) * BSTRIDE + cw + grp;
            const uint32_t* br1 = br0 + 4 * BSTRIDE;
            #pragma unroll
            for (int nt = 0; nt < 8; nt++) {
                uint32_t b0 = br0[nt * 8];
                uint32_t b1v = br1[nt * 8];
                mma_tf32(acc[0][nt], a0[0], a1[0], a2[0], a3[0], b0, b1v);
                mma_tf32(acc[1][nt], a0[1], a1[1], a2[1], a3[1], b0, b1v);
            }
        }

        // ---- epilogue: h2 = relu(c + b2), partial logit = sum W3*h2 ----
        float pl[2][2] = {{0.f, 0.f}, {0.f, 0.f}};
        #pragma unroll
        for (int mt = 0; mt < 2; mt++)
            #pragma unroll
            for (int nt = 0; nt < 8; nt++) {
                int c0 = cw + nt * 8 + tig * 2;
                float b2a = s->b2s[c0],     b2b = s->b2s[c0 + 1];
                float w3a = s->w3s[c0],     w3b = s->w3s[c0 + 1];
                pl[mt][0] = fmaf(w3a, fmaxf(acc[mt][nt][0] + b2a, 0.f), pl[mt][0]);
                pl[mt][0] = fmaf(w3b, fmaxf(acc[mt][nt][1] + b2b, 0.f), pl[mt][0]);
                pl[mt][1] = fmaf(w3a, fmaxf(acc[mt][nt][2] + b2a, 0.f), pl[mt][1]);
                pl[mt][1] = fmaf(w3b, fmaxf(acc[mt][nt][3] + b2b, 0.f), pl[mt][1]);
            }
        #pragma unroll
        for (int mt = 0; mt < 2; mt++) {
            pl[mt][0] += __shfl_xor_sync(0xffffffffu, pl[mt][0], 1);
            pl[mt][0] += __shfl_xor_sync(0xffffffffu, pl[mt][0], 2);
            pl[mt][1] += __shfl_xor_sync(0xffffffffu, pl[mt][1], 1);
            pl[mt][1] += __shfl_xor_sync(0xffffffffu, pl[mt][1], 2);
            if (tig == 0) {
                atomicAdd(&s->logit[g][mw + mt * 16 + grp],     pl[mt][0]);
                atomicAdd(&s->logit[g][mw + mt * 16 + grp + 8], pl[mt][1]);
            }
        }
        gsync4(g);

        // ---- masked softmax over K, warps 0/1 of the group (one per node) ----
        if (wg < 2) {
            int nn = wg;
            int len = nlen[task * 2 + nn];
            float lg = s->logit[g][nn * KK + lane] + b3v;
            bool valid = lane < len;
            float v = valid ? lg : -3.0e38f;
            float m = wmaxf(v);
            float ex = valid ? expf(lg - m) : 0.f;
            float sm = wsumf(ex);
            s->att[g][nn * KK + lane] = (len > 0) ? (ex / sm) : 0.f;
        }
        gsync4(g);

        // ---- aggregation + output (exact fp32): thread tg -> dim d, both nodes ----
        {
            int d = tg;
            #pragma unroll
            for (int nn = 0; nn < 2; nn++) {
                int n = task * 2 + nn;
                float self = u2e[(size_t)nodes[n] * DD + d];
                float o;
                if (nlen[n] > 0) {
                    float agg = 0.f;
                    #pragma unroll
                    for (int k = 0; k < KK; k++)
                        agg = fmaf(s->att[g][nn * KK + k],
                                   u2e[(size_t)s->idx[g][nn * KK + k] * DD + d], agg);
                    o = 0.5f * (agg + self);
                } else {
                    o = self;
                }
                out[(size_t)n * DD + d] = o;
            }
        }
    }
}

// ---------------- launcher ----------------
extern "C" void kernel_launch(void* const* d_in, const int* in_sizes, int n_in,
                              void* d_out, int out_size) {
    const int*   nodes = (const int*)d_in[0];
    const int*   nidx  = (const int*)d_in[1];
    const int*   nlen  = (const int*)d_in[2];
    const float* u2e   = (const float*)d_in[3];
    const float* W1    = (const float*)d_in[4];
    const float* b1    = (const float*)d_in[5];
    const float* W2    = (const float*)d_in[6];
    const float* b2    = (const float*)d_in[7];
    const float* W3    = (const float*)d_in[8];
    const float* b3    = (const float*)d_in[9];
    float* out = (float*)d_out;

    cudaFuncSetAttribute(mlp_tc2_kernel,  cudaFuncAttributeMaxDynamicSharedMemorySize, (int)sizeof(SM3));
    cudaFuncSetAttribute(graphrec_kernel, cudaFuncAttributeMaxDynamicSharedMemorySize, (int)sizeof(SK4));

    const int SMS = 152;   // GB300: 152 SMs, one resident block each (smem-bound)
    int tasksT   = (VOCAB + 63) / 64;          // 1563
    int tasksC   = (NN + 63) / 64;             // 313
    int tasksAll = tasksT + tasksC;            // 1876
    int tasksG   = NN / 2;                     // 10000 (2 nodes per task)

    int gM = (tasksAll + 1) / 2; if (gM > SMS) gM = SMS;
    int gG = (tasksG + 3) / 4;   if (gG > SMS) gG = SMS;

    prep_kernel<<<(DD * DD + 255) / 256, 256>>>(W1, W2);
    mlp_tc2_kernel<<<gM, 512, sizeof(SM3)>>>(u2e, nodes, b1, tasksT, tasksAll);
    graphrec_kernel<<<gG, 512, sizeof(SK4)>>>(u2e, nodes, nidx, nlen, b2, W3, b3, out, tasksG);
}